// round 2
// baseline (speedup 1.0000x reference)
#include <cuda_runtime.h>

#define BSZ 128
#define LPAST 365
#define HHOR 8
#define TSEQ 372
#define DIN 32
#define NSTATIC 27
#define HID 1024
#define G4 4096
#define TEMBD 256
#define KTOT 1088
#define NCTA 128
#define TPB 256
#define JC 8
#define GD 32
#define CHUNK 32
#define NCHUNK 34
#define SMEMB 196608

__device__ float    g_h[2][HID * BSZ];
__device__ float    g_bias[BSZ * G4];
__device__ float    g_temb[BSZ * HID];
__device__ float    g_xT[TSEQ * 64 * BSZ];
__device__ float    g_part[NCTA * HHOR * BSZ];
__device__ unsigned g_cnt;

__device__ __forceinline__ float sigm(float x) { return 1.f / (1.f + expf(-x)); }

__global__ void setup_kernel(const float* __restrict__ x_past,
                             const float* __restrict__ noisy_future,
                             const float* __restrict__ tval,
                             const float* __restrict__ x_future,
                             const float* __restrict__ static_attr,
                             const float* __restrict__ W_ih,
                             const float* __restrict__ b_ih,
                             const float* __restrict__ b_hh,
                             const float* __restrict__ freqs,
                             const float* __restrict__ phases,
                             const float* __restrict__ W1,
                             const float* __restrict__ b1,
                             const float* __restrict__ W2,
                             const float* __restrict__ b2)
{
    const int tid = threadIdx.x;
    const int blk = blockIdx.x;
    __shared__ float emb[TEMBD];
    __shared__ float hm[2 * TEMBD];
    __shared__ float st[NSTATIC];

    if (blk < BSZ) {
        const int b = blk;
        const float tv = tval[b];
        if (tid < TEMBD)
            emb[tid] = cosf(tv * freqs[tid] + phases[tid]) * 1.41421356237309515f;
        __syncthreads();
        for (int u = tid; u < 2 * TEMBD; u += TPB) {
            float s = b1[u];
            const float* w = W1 + u * TEMBD;
            #pragma unroll 4
            for (int k = 0; k < TEMBD; ++k) s += emb[k] * w[k];
            hm[u] = s * sigm(s);
        }
        __syncthreads();
        for (int h = tid; h < HID; h += TPB) {
            float s = b2[h];
            const float* w = W2 + h * 2 * TEMBD;
            #pragma unroll 4
            for (int u = 0; u < 2 * TEMBD; ++u) s += hm[u] * w[u];
            g_temb[b * HID + h] = s;
        }
    } else {
        const int b = blk - BSZ;
        if (tid < NSTATIC) st[tid] = static_attr[b * NSTATIC + tid];
        __syncthreads();
        for (int r = tid; r < G4; r += TPB) {
            float s = b_ih[r] + b_hh[r];
            const float* w = W_ih + r * 60 + 33;
            #pragma unroll
            for (int k = 0; k < NSTATIC; ++k) s += st[k] * w[k];
            g_bias[b * G4 + r] = s;
        }
        for (int idx = tid; idx < TSEQ * 64; idx += TPB) {
            const int t = idx >> 6, m = idx & 63;
            float v = 0.f;
            if (m < 32)
                v = (t < LPAST) ? x_past[(b * LPAST + t) * DIN + m]
                                : x_future[(b * (HHOR - 1) + (t - LPAST)) * DIN + m];
            else if (m == 32)
                v = (t >= LPAST - 1) ? noisy_future[b * HHOR + (t - (LPAST - 1))] : 0.f;
            g_xT[idx * BSZ + b] = v;
        }
        for (int i = tid; i < HID; i += TPB)
            g_h[0][b * HID + i] = 0.f;
        if (b == 0 && tid == 0) g_cnt = 0u;
    }
}

__global__ void __launch_bounds__(TPB, 1)
lstm_main(const float* __restrict__ W_hh,
          const float* __restrict__ W_ih,
          const float* __restrict__ Wh)
{
    extern __shared__ float sm[];
    float* Wt     = sm;                           // [KTOT][GD]
    float* Hs     = Wt + KTOT * GD;               // [2][CHUNK*BSZ]
    float* bias_s = Hs + 2 * CHUNK * BSZ;         // [GD][BSZ]
    float* temb_s = bias_s + GD * BSZ;            // [JC][BSZ]
    float* red    = temb_s + JC * BSZ;            // [JC][BSZ]

    const int tid = threadIdx.x;
    const int bt  = tid & 31;
    const int gdt = tid >> 5;
    const int cta = blockIdx.x;
    const int j0  = cta * JC;

    for (int idx = tid; idx < GD * KTOT; idx += TPB) {
        const int gd = idx / KTOT, k = idx - gd * KTOT;
        const int jloc = gd >> 2, gate = gd & 3;
        const int r = gate * HID + j0 + jloc;
        float v;
        if (k < HID)            v = W_hh[r * HID + k];
        else if (k < HID + 33)  v = W_ih[r * 60 + (k - HID)];
        else                    v = 0.f;
        Wt[k * GD + gd] = v;
    }
    for (int idx = tid; idx < GD * BSZ; idx += TPB) {
        const int gd = idx >> 7, b = idx & 127;
        const int jloc = gd >> 2, gate = gd & 3;
        bias_s[gd * BSZ + b] = g_bias[b * G4 + gate * HID + j0 + jloc];
    }
    for (int idx = tid; idx < JC * BSZ; idx += TPB) {
        const int jl = idx >> 7, b = idx & 127;
        temb_s[idx] = g_temb[b * HID + j0 + jl];
    }
    const float whv = Wh[j0 + gdt];
    __syncthreads();

    float c0 = 0.f, c1 = 0.f, c2 = 0.f, c3 = 0.f;

    for (int t = 0; t < TSEQ; ++t) {
        const float* hsrc = g_h[t & 1];
        const float* xsrc = g_xT + t * 64 * BSZ;

        float4 a0 = *(const float4*)(bias_s + (gdt * 4 + 0) * BSZ + bt * 4);
        float4 a1 = *(const float4*)(bias_s + (gdt * 4 + 1) * BSZ + bt * 4);
        float4 a2 = *(const float4*)(bias_s + (gdt * 4 + 2) * BSZ + bt * 4);
        float4 a3 = *(const float4*)(bias_s + (gdt * 4 + 3) * BSZ + bt * 4);

        float4 p0, p1, p2, p3;
        {
            const float4* s = (const float4*)hsrc + tid;
            p0 = __ldcg(s); p1 = __ldcg(s + 256); p2 = __ldcg(s + 512); p3 = __ldcg(s + 768);
        }

        for (int c = 0; c < NCHUNK; ++c) {
            float4* hb = (float4*)(Hs + (c & 1) * CHUNK * BSZ);
            hb[tid] = p0; hb[tid + 256] = p1; hb[tid + 512] = p2; hb[tid + 768] = p3;
            __syncthreads();
            if (c + 1 < NCHUNK) {
                const float* base = (c + 1 < 32) ? (hsrc + (c + 1) * CHUNK * BSZ)
                                                 : (xsrc + (c + 1 - 32) * CHUNK * BSZ);
                const float4* s = (const float4*)base + tid;
                p0 = __ldcg(s); p1 = __ldcg(s + 256); p2 = __ldcg(s + 512); p3 = __ldcg(s + 768);
            }
            const float* hbc = Hs + (c & 1) * CHUNK * BSZ + bt * 4;
            const float* wb  = Wt + (c * CHUNK) * GD + gdt * 4;
            #pragma unroll
            for (int kk = 0; kk < CHUNK; ++kk) {
                const float4 hv = *(const float4*)(hbc + kk * BSZ);
                const float4 wv = *(const float4*)(wb + kk * GD);
                a0.x = fmaf(wv.x, hv.x, a0.x); a0.y = fmaf(wv.x, hv.y, a0.y);
                a0.z = fmaf(wv.x, hv.z, a0.z); a0.w = fmaf(wv.x, hv.w, a0.w);
                a1.x = fmaf(wv.y, hv.x, a1.x); a1.y = fmaf(wv.y, hv.y, a1.y);
                a1.z = fmaf(wv.y, hv.z, a1.z); a1.w = fmaf(wv.y, hv.w, a1.w);
                a2.x = fmaf(wv.z, hv.x, a2.x); a2.y = fmaf(wv.z, hv.y, a2.y);
                a2.z = fmaf(wv.z, hv.z, a2.z); a2.w = fmaf(wv.z, hv.w, a2.w);
                a3.x = fmaf(wv.w, hv.x, a3.x); a3.y = fmaf(wv.w, hv.y, a3.y);
                a3.z = fmaf(wv.w, hv.z, a3.z); a3.w = fmaf(wv.w, hv.w, a3.w);
            }
        }

        const bool addte = (t == 363);
        float4 te = make_float4(0.f, 0.f, 0.f, 0.f);
        if (addte) te = *(const float4*)(temb_s + gdt * BSZ + bt * 4);
        float4 hw;
        {
            float iv = sigm(a0.x), fv = sigm(a1.x), gv = tanhf(a2.x), ov = sigm(a3.x);
            c0 = fv * c0 + iv * gv; float hn = ov * tanhf(c0);
            if (addte) { hn += te.x; c0 += te.x; } hw.x = hn;
        }
        {
            float iv = sigm(a0.y), fv = sigm(a1.y), gv = tanhf(a2.y), ov = sigm(a3.y);
            c1 = fv * c1 + iv * gv; float hn = ov * tanhf(c1);
            if (addte) { hn += te.y; c1 += te.y; } hw.y = hn;
        }
        {
            float iv = sigm(a0.z), fv = sigm(a1.z), gv = tanhf(a2.z), ov = sigm(a3.z);
            c2 = fv * c2 + iv * gv; float hn = ov * tanhf(c2);
            if (addte) { hn += te.z; c2 += te.z; } hw.z = hn;
        }
        {
            float iv = sigm(a0.w), fv = sigm(a1.w), gv = tanhf(a2.w), ov = sigm(a3.w);
            c3 = fv * c3 + iv * gv; float hn = ov * tanhf(c3);
            if (addte) { hn += te.w; c3 += te.w; } hw.w = hn;
        }
        *(float4*)(g_h[(t + 1) & 1] + (j0 + gdt) * BSZ + bt * 4) = hw;

        if (t >= 364) {
            *(float4*)(red + gdt * BSZ + bt * 4) =
                make_float4(hw.x * whv, hw.y * whv, hw.z * whv, hw.w * whv);
            __syncthreads();
            if (tid < BSZ) {
                float s = 0.f;
                #pragma unroll
                for (int jl = 0; jl < JC; ++jl) s += red[jl * BSZ + tid];
                g_part[(cta * HHOR + (t - 364)) * BSZ + tid] = s;
            }
        }

        __threadfence();
        __syncthreads();
        if (tid == 0) {
            atomicAdd(&g_cnt, 1u);
            const unsigned target = (unsigned)(t + 1) * NCTA;
            while (*((volatile unsigned*)&g_cnt) < target) { __nanosleep(32); }
            __threadfence();
        }
        __syncthreads();
    }
}

__global__ void out_kernel(const float* __restrict__ bh, float* __restrict__ out)
{
    const int idx = blockIdx.x * blockDim.x + threadIdx.x;
    if (idx >= BSZ * HHOR) return;
    const int b = idx >> 3, tf = idx & 7;
    float s = bh[0];
    #pragma unroll 4
    for (int c = 0; c < NCTA; ++c)
        s += g_part[(c * HHOR + tf) * BSZ + b];
    out[idx] = s;
}

extern "C" void kernel_launch(void* const* d_in, const int* in_sizes, int n_in,
                              void* d_out, int out_size)
{
    cudaFuncSetAttribute(lstm_main, cudaFuncAttributeMaxDynamicSharedMemorySize, SMEMB);
    setup_kernel<<<2 * BSZ, TPB>>>(
        (const float*)d_in[0], (const float*)d_in[1], (const float*)d_in[2],
        (const float*)d_in[3], (const float*)d_in[4], (const float*)d_in[5],
        (const float*)d_in[7], (const float*)d_in[8], (const float*)d_in[9],
        (const float*)d_in[10], (const float*)d_in[11], (const float*)d_in[12],
        (const float*)d_in[13], (const float*)d_in[14]);
    lstm_main<<<NCTA, TPB, SMEMB>>>(
        (const float*)d_in[6], (const float*)d_in[5], (const float*)d_in[15]);
    out_kernel<<<(BSZ * HHOR + TPB - 1) / TPB, TPB>>>(
        (const float*)d_in[16], (float*)d_out);
}